// round 1
// baseline (speedup 1.0000x reference)
#include <cuda_runtime.h>
#include <cuda_bf16.h>
#include <cstdint>

// ---------------------------------------------------------------------------
// GraphNet (jraph-style) fused kernels.
//   N=100k nodes, E=3.2M edges, F=32, LATENT=5.
//   HBM-bound on edge_feats (410MB). All per-edge math folded to minimum.
// ---------------------------------------------------------------------------

#define NMAX 131072          // >= 100000 nodes, padded
#define THREADS 256

// Scratch (static device memory; no runtime allocation)
__device__ float d_nemb [NMAX * 8];   // node embedding n        [N][8] (5 used)
__device__ float d_sproj[NMAX * 8];   // n @ We1[5:10]           [N][8]
__device__ float d_rproj[NMAX * 8];   // n @ We1[10:15]          [N][8]
__device__ float d_sent [NMAX * 8];   // segment_sum over senders
__device__ float d_recv [NMAX * 8];   // segment_sum over receivers
__device__ float d_wcomb[32 * 8];     // W_edge_emb @ We1[0:5]   [32][8] (5 used)
__device__ float d_hbase[8];          // be1 + b_edge@We1[0:5] + g@We1[15:20]
__device__ float d_gnbase[8];         // bn1 + g@Wn1[15:20]

// ---------------------------------------------------------------------------
// Kernel 0: tiny precompute (1 block).
// ---------------------------------------------------------------------------
__global__ void prep_kernel(const float* __restrict__ gfeat,      // [1,32]
                            const float* __restrict__ Wg,         // [32,5]
                            const float* __restrict__ bg,         // [5]
                            const float* __restrict__ b_edge,     // [5]
                            const float* __restrict__ We1,        // [20,5]
                            const float* __restrict__ be1,        // [5]
                            const float* __restrict__ W_edge,     // [32,5]
                            const float* __restrict__ Wn1,        // [20,5]
                            const float* __restrict__ bn1)        // [5]
{
    __shared__ float g[5];
    int t = threadIdx.x;

    if (t < 5) {
        float acc = bg[t];
        #pragma unroll 8
        for (int k = 0; k < 32; k++) acc += gfeat[k] * Wg[k * 5 + t];
        g[t] = acc;
    }
    __syncthreads();

    if (t < 5) {
        float hb = be1[t];
        float gn = bn1[t];
        #pragma unroll
        for (int m = 0; m < 5; m++) {
            hb += b_edge[m] * We1[m * 5 + t];
            hb += g[m]      * We1[(15 + m) * 5 + t];
            gn += g[m]      * Wn1[(15 + m) * 5 + t];
        }
        d_hbase[t]  = hb;
        d_gnbase[t] = gn;
    }
    // W_comb[k][j] = sum_m W_edge[k][m] * We1[m][j]
    if (t < 160) {
        int k = t / 5, j = t % 5;
        float acc = 0.f;
        #pragma unroll
        for (int m = 0; m < 5; m++) acc += W_edge[k * 5 + m] * We1[m * 5 + j];
        d_wcomb[k * 8 + j] = acc;
    }
    // zero pads of wcomb rows (so float4 smem loads are well-defined)
    if (t >= 192 && t < 224) {
        int k = t - 192;
        d_wcomb[k * 8 + 5] = 0.f; d_wcomb[k * 8 + 6] = 0.f; d_wcomb[k * 8 + 7] = 0.f;
    }
    if (t >= 224 && t < 227) { d_hbase[5 + (t - 224)] = 0.f; d_gnbase[5 + (t - 224)] = 0.f; }
}

// ---------------------------------------------------------------------------
// Kernel 1: node pre-pass. n = node_feats@W_node + b ; sproj/rproj ; zero aggs.
// ---------------------------------------------------------------------------
__global__ void node_pre_kernel(const float* __restrict__ nf,     // [N,32]
                                const float* __restrict__ Wn,     // [32,5]
                                const float* __restrict__ bn,     // [5]
                                const float* __restrict__ We1,    // [20,5]
                                int N)
{
    __shared__ float s_Wn[160];
    __shared__ float s_bn[5];
    __shared__ float s_W1s[25];   // We1 rows 5..9
    __shared__ float s_W1r[25];   // We1 rows 10..14
    int t = threadIdx.x;
    for (int j = t; j < 160; j += THREADS) s_Wn[j] = Wn[j];
    if (t < 5)  s_bn[t]  = bn[t];
    if (t < 25) s_W1s[t] = We1[25 + t];
    if (t < 25) s_W1r[t] = We1[50 + t];
    __syncthreads();

    int n = blockIdx.x * THREADS + t;
    if (n >= N) return;

    const float4* x4 = (const float4*)(nf + (size_t)n * 32);
    float a0 = s_bn[0], a1 = s_bn[1], a2 = s_bn[2], a3 = s_bn[3], a4 = s_bn[4];
    #pragma unroll
    for (int c = 0; c < 8; c++) {
        float4 xv = __ldg(&x4[c]);
        const float xs[4] = {xv.x, xv.y, xv.z, xv.w};
        #pragma unroll
        for (int kk = 0; kk < 4; kk++) {
            int k = c * 4 + kk;
            float x = xs[kk];
            a0 += x * s_Wn[k * 5 + 0];
            a1 += x * s_Wn[k * 5 + 1];
            a2 += x * s_Wn[k * 5 + 2];
            a3 += x * s_Wn[k * 5 + 3];
            a4 += x * s_Wn[k * 5 + 4];
        }
    }

    // write node embedding (padded row)
    *(float4*)&d_nemb[n * 8 + 0] = make_float4(a0, a1, a2, a3);
    *(float4*)&d_nemb[n * 8 + 4] = make_float4(a4, 0.f, 0.f, 0.f);

    // sender / receiver projections
    float s0 = 0, s1 = 0, s2 = 0, s3 = 0, s4 = 0;
    float r0 = 0, r1 = 0, r2 = 0, r3 = 0, r4 = 0;
    const float nm[5] = {a0, a1, a2, a3, a4};
    #pragma unroll
    for (int m = 0; m < 5; m++) {
        float v = nm[m];
        s0 += v * s_W1s[m * 5 + 0]; s1 += v * s_W1s[m * 5 + 1]; s2 += v * s_W1s[m * 5 + 2];
        s3 += v * s_W1s[m * 5 + 3]; s4 += v * s_W1s[m * 5 + 4];
        r0 += v * s_W1r[m * 5 + 0]; r1 += v * s_W1r[m * 5 + 1]; r2 += v * s_W1r[m * 5 + 2];
        r3 += v * s_W1r[m * 5 + 3]; r4 += v * s_W1r[m * 5 + 4];
    }
    *(float4*)&d_sproj[n * 8 + 0] = make_float4(s0, s1, s2, s3);
    *(float4*)&d_sproj[n * 8 + 4] = make_float4(s4, 0.f, 0.f, 0.f);
    *(float4*)&d_rproj[n * 8 + 0] = make_float4(r0, r1, r2, r3);
    *(float4*)&d_rproj[n * 8 + 4] = make_float4(r4, 0.f, 0.f, 0.f);

    // zero aggregation buffers for this launch (graph replay safe)
    float4 z = make_float4(0.f, 0.f, 0.f, 0.f);
    *(float4*)&d_sent[n * 8 + 0] = z; *(float4*)&d_sent[n * 8 + 4] = z;
    *(float4*)&d_recv[n * 8 + 0] = z; *(float4*)&d_recv[n * 8 + 4] = z;
}

// ---------------------------------------------------------------------------
// Kernel 2: fused edge pass. Dominant kernel (reads 410MB of edge_feats).
//   h  = relu(edge_feats@W_comb + sproj[s] + rproj[r] + h_base)
//   e2 = relu(h @ We2 + be2)
//   atomically accumulate e2 into sent[s] and recv[r].
// ---------------------------------------------------------------------------
__global__ void __launch_bounds__(THREADS)
edge_kernel(const float* __restrict__ ef,     // [E,32]
            const int*   __restrict__ snd,    // [E]
            const int*   __restrict__ rcv,    // [E]
            const float* __restrict__ We2,    // [5,5]
            const float* __restrict__ be2,    // [5]
            int E)
{
    __shared__ float s_wc[256];   // d_wcomb [32][8]
    __shared__ float s_w2[25];
    __shared__ float s_b2[5];
    __shared__ float s_hb[5];
    int t = threadIdx.x;
    if (t < 64) ((float4*)s_wc)[t] = ((const float4*)d_wcomb)[t];
    if (t >= 64  && t < 89)  s_w2[t - 64] = We2[t - 64];
    if (t >= 96  && t < 101) s_b2[t - 96] = be2[t - 96];
    if (t >= 104 && t < 109) s_hb[t - 104] = d_hbase[t - 104];
    __syncthreads();

    int i = blockIdx.x * THREADS + t;
    if (i >= E) return;

    // load the edge feature row (128B)
    const float4* x4 = (const float4*)(ef + (size_t)i * 32);
    float4 x[8];
    #pragma unroll
    for (int c = 0; c < 8; c++) x[c] = __ldg(&x4[c]);

    int s = __ldg(&snd[i]);
    int r = __ldg(&rcv[i]);

    float a0 = s_hb[0], a1 = s_hb[1], a2 = s_hb[2], a3 = s_hb[3], a4 = s_hb[4];
    #pragma unroll
    for (int c = 0; c < 8; c++) {
        const float xs[4] = {x[c].x, x[c].y, x[c].z, x[c].w};
        #pragma unroll
        for (int kk = 0; kk < 4; kk++) {
            int k = c * 4 + kk;
            float xv = xs[kk];
            float4 w = *(const float4*)&s_wc[k * 8];
            float  w4 = s_wc[k * 8 + 4];
            a0 += xv * w.x; a1 += xv * w.y; a2 += xv * w.z; a3 += xv * w.w;
            a4 += xv * w4;
        }
    }

    // gather precomputed node projections (each one 32B sector, L2-resident)
    float4 sp = *(const float4*)&d_sproj[(size_t)s * 8];
    float  sp4 = d_sproj[(size_t)s * 8 + 4];
    float4 rp = *(const float4*)&d_rproj[(size_t)r * 8];
    float  rp4 = d_rproj[(size_t)r * 8 + 4];

    float h0 = fmaxf(a0 + sp.x + rp.x, 0.f);
    float h1 = fmaxf(a1 + sp.y + rp.y, 0.f);
    float h2 = fmaxf(a2 + sp.z + rp.z, 0.f);
    float h3 = fmaxf(a3 + sp.w + rp.w, 0.f);
    float h4 = fmaxf(a4 + sp4  + rp4 , 0.f);

    // MLP layer 2: e2 = relu(h @ We2 + be2)
    float o0 = s_b2[0], o1 = s_b2[1], o2 = s_b2[2], o3 = s_b2[3], o4 = s_b2[4];
    const float hh[5] = {h0, h1, h2, h3, h4};
    #pragma unroll
    for (int k = 0; k < 5; k++) {
        float hv = hh[k];
        o0 += hv * s_w2[k * 5 + 0];
        o1 += hv * s_w2[k * 5 + 1];
        o2 += hv * s_w2[k * 5 + 2];
        o3 += hv * s_w2[k * 5 + 3];
        o4 += hv * s_w2[k * 5 + 4];
    }
    o0 = fmaxf(o0, 0.f); o1 = fmaxf(o1, 0.f); o2 = fmaxf(o2, 0.f);
    o3 = fmaxf(o3, 0.f); o4 = fmaxf(o4, 0.f);

    // scatter-reduce (segment_sum): vector float4 atomics (sm_90+) + scalar
    float4 ov = make_float4(o0, o1, o2, o3);
    atomicAdd((float4*)&d_sent[(size_t)s * 8], ov);
    atomicAdd(&d_sent[(size_t)s * 8 + 4], o4);
    atomicAdd((float4*)&d_recv[(size_t)r * 8], ov);
    atomicAdd(&d_recv[(size_t)r * 8 + 4], o4);
}

// ---------------------------------------------------------------------------
// Kernel 3: node update epilogue.
//   h2 = relu(n@Wn1[0:5] + sent@Wn1[5:10] + recv@Wn1[10:15] + gn_base)
//   out = relu(h2 @ Wn2 + bn2)
// ---------------------------------------------------------------------------
__global__ void node_out_kernel(const float* __restrict__ Wn1,   // [20,5]
                                const float* __restrict__ Wn2,   // [5,5]
                                const float* __restrict__ bn2,   // [5]
                                float* __restrict__ out,         // [N,5]
                                int N)
{
    __shared__ float s_w1[75];   // rows 0..14 of Wn1
    __shared__ float s_w2[25];
    __shared__ float s_b2[5];
    __shared__ float s_gb[5];
    int t = threadIdx.x;
    if (t < 75) s_w1[t] = Wn1[t];
    if (t >= 96 && t < 121) s_w2[t - 96] = Wn2[t - 96];
    if (t >= 128 && t < 133) s_b2[t - 128] = bn2[t - 128];
    if (t >= 136 && t < 141) s_gb[t - 136] = d_gnbase[t - 136];
    __syncthreads();

    int n = blockIdx.x * THREADS + t;
    if (n >= N) return;

    float4 nv  = *(const float4*)&d_nemb[(size_t)n * 8];
    float  nv4 = d_nemb[(size_t)n * 8 + 4];
    float4 sv  = *(const float4*)&d_sent[(size_t)n * 8];
    float  sv4 = d_sent[(size_t)n * 8 + 4];
    float4 rv  = *(const float4*)&d_recv[(size_t)n * 8];
    float  rv4 = d_recv[(size_t)n * 8 + 4];

    const float nn[5] = {nv.x, nv.y, nv.z, nv.w, nv4};
    const float ss[5] = {sv.x, sv.y, sv.z, sv.w, sv4};
    const float rr[5] = {rv.x, rv.y, rv.z, rv.w, rv4};

    float h[5];
    #pragma unroll
    for (int j = 0; j < 5; j++) {
        float acc = s_gb[j];
        #pragma unroll
        for (int m = 0; m < 5; m++) {
            acc += nn[m] * s_w1[m * 5 + j];
            acc += ss[m] * s_w1[(5 + m) * 5 + j];
            acc += rr[m] * s_w1[(10 + m) * 5 + j];
        }
        h[j] = fmaxf(acc, 0.f);
    }
    #pragma unroll
    for (int j = 0; j < 5; j++) {
        float acc = s_b2[j];
        #pragma unroll
        for (int k = 0; k < 5; k++) acc += h[k] * s_w2[k * 5 + j];
        out[(size_t)n * 5 + j] = fmaxf(acc, 0.f);
    }
}

// ---------------------------------------------------------------------------
extern "C" void kernel_launch(void* const* d_in, const int* in_sizes, int n_in,
                              void* d_out, int out_size)
{
    const float* node_feats  = (const float*)d_in[0];
    const float* edge_feats  = (const float*)d_in[1];
    const float* global_feat = (const float*)d_in[2];
    const int*   senders     = (const int*)  d_in[3];
    const int*   receivers   = (const int*)  d_in[4];
    const float* W_edge_emb  = (const float*)d_in[5];
    const float* b_edge_emb  = (const float*)d_in[6];
    const float* W_node_emb  = (const float*)d_in[7];
    const float* b_node_emb  = (const float*)d_in[8];
    const float* W_glob_emb  = (const float*)d_in[9];
    const float* b_glob_emb  = (const float*)d_in[10];
    const float* We1         = (const float*)d_in[11];
    const float* be1         = (const float*)d_in[12];
    const float* We2         = (const float*)d_in[13];
    const float* be2         = (const float*)d_in[14];
    const float* Wn1         = (const float*)d_in[15];
    const float* bn1         = (const float*)d_in[16];
    const float* Wn2         = (const float*)d_in[17];
    const float* bn2         = (const float*)d_in[18];
    float* out = (float*)d_out;

    int N = in_sizes[0] / 32;
    int E = in_sizes[1] / 32;

    prep_kernel<<<1, 256>>>(global_feat, W_glob_emb, b_glob_emb,
                            b_edge_emb, We1, be1, W_edge_emb, Wn1, bn1);

    node_pre_kernel<<<(N + THREADS - 1) / THREADS, THREADS>>>(
        node_feats, W_node_emb, b_node_emb, We1, N);

    edge_kernel<<<(E + THREADS - 1) / THREADS, THREADS>>>(
        edge_feats, senders, receivers, We2, be2, E);

    node_out_kernel<<<(N + THREADS - 1) / THREADS, THREADS>>>(
        Wn1, Wn2, bn2, out, N);
}

// round 3
// speedup vs baseline: 1.0278x; 1.0278x over previous
#include <cuda_runtime.h>
#include <cuda_bf16.h>
#include <cstdint>

// ---------------------------------------------------------------------------
// GraphNet fused kernels, round 3 (re-run of round-2 design; prior bench was
// an infra failure).
//   Edge kernel is wavefront/issue bound, not DRAM bound. Design:
//   2 edges/thread (amortize weight LDS), transposed weights, __ldcs streaming
//   on the 410MB edge stream (protect L2-resident hot arrays), split
//   float4/scalar planes for gathers and atomics.
// ---------------------------------------------------------------------------

#define NMAX 131072
#define THREADS 256
#define EPB (2 * THREADS)    // edges per block

// ---- scratch (static device memory) ----
__device__ float4 d_nemb4 [NMAX];    __device__ float d_nemb1 [NMAX];
__device__ float4 d_projs4[NMAX];    __device__ float d_projs1[NMAX];
__device__ float4 d_projr4[NMAX];    __device__ float d_projr1[NMAX];
__device__ float4 d_accs4 [NMAX];    __device__ float d_accs1 [NMAX];
__device__ float4 d_accr4 [NMAX];    __device__ float d_accr1 [NMAX];
__device__ float4 d_wcombT[40];      // [c=8][j=5], float4 over kk: W_comb[4c+kk][j]
__device__ float  d_hbase[5];
__device__ float  d_gnbase[5];

// ---------------------------------------------------------------------------
// Kernel 0: tiny precompute (1 block).
// ---------------------------------------------------------------------------
__global__ void prep_kernel(const float* __restrict__ gfeat,
                            const float* __restrict__ Wg,
                            const float* __restrict__ bg,
                            const float* __restrict__ b_edge,
                            const float* __restrict__ We1,
                            const float* __restrict__ be1,
                            const float* __restrict__ W_edge,
                            const float* __restrict__ Wn1,
                            const float* __restrict__ bn1)
{
    __shared__ float g[5];
    int t = threadIdx.x;

    if (t < 5) {
        float acc = bg[t];
        #pragma unroll 8
        for (int k = 0; k < 32; k++) acc += gfeat[k] * Wg[k * 5 + t];
        g[t] = acc;
    }
    __syncthreads();

    if (t < 5) {
        float hb = be1[t];
        float gn = bn1[t];
        #pragma unroll
        for (int m = 0; m < 5; m++) {
            hb += b_edge[m] * We1[m * 5 + t];
            hb += g[m]      * We1[(15 + m) * 5 + t];
            gn += g[m]      * Wn1[(15 + m) * 5 + t];
        }
        d_hbase[t]  = hb;
        d_gnbase[t] = gn;
    }
    // transposed combined weight: (c, j, kk) = sum_m W_edge[4c+kk][m]*We1[m][j]
    if (t < 160) {
        int c = t / 20, rem = t % 20, j = rem / 4, kk = rem % 4;
        int k = 4 * c + kk;
        float acc = 0.f;
        #pragma unroll
        for (int m = 0; m < 5; m++) acc += W_edge[k * 5 + m] * We1[m * 5 + j];
        ((float*)d_wcombT)[(c * 5 + j) * 4 + kk] = acc;
    }
}

// ---------------------------------------------------------------------------
// Kernel 1: node pre-pass: embed, project, zero accumulators.
// ---------------------------------------------------------------------------
__global__ void node_pre_kernel(const float* __restrict__ nf,
                                const float* __restrict__ Wn,
                                const float* __restrict__ bn,
                                const float* __restrict__ We1,
                                int N)
{
    __shared__ float s_Wn[160];
    __shared__ float s_bn[5];
    __shared__ float s_W1s[25];
    __shared__ float s_W1r[25];
    int t = threadIdx.x;
    for (int j = t; j < 160; j += THREADS) s_Wn[j] = Wn[j];
    if (t < 5)  s_bn[t]  = bn[t];
    if (t < 25) s_W1s[t] = We1[25 + t];
    if (t < 25) s_W1r[t] = We1[50 + t];
    __syncthreads();

    int n = blockIdx.x * THREADS + t;
    if (n >= N) return;

    const float4* x4 = (const float4*)(nf + (size_t)n * 32);
    float a0 = s_bn[0], a1 = s_bn[1], a2 = s_bn[2], a3 = s_bn[3], a4 = s_bn[4];
    #pragma unroll
    for (int c = 0; c < 8; c++) {
        float4 xv = __ldg(&x4[c]);
        const float xs[4] = {xv.x, xv.y, xv.z, xv.w};
        #pragma unroll
        for (int kk = 0; kk < 4; kk++) {
            int k = c * 4 + kk;
            float x = xs[kk];
            a0 += x * s_Wn[k * 5 + 0];
            a1 += x * s_Wn[k * 5 + 1];
            a2 += x * s_Wn[k * 5 + 2];
            a3 += x * s_Wn[k * 5 + 3];
            a4 += x * s_Wn[k * 5 + 4];
        }
    }

    d_nemb4[n] = make_float4(a0, a1, a2, a3);
    d_nemb1[n] = a4;

    float s0 = 0, s1 = 0, s2 = 0, s3 = 0, s4 = 0;
    float r0 = 0, r1 = 0, r2 = 0, r3 = 0, r4 = 0;
    const float nm[5] = {a0, a1, a2, a3, a4};
    #pragma unroll
    for (int m = 0; m < 5; m++) {
        float v = nm[m];
        s0 += v * s_W1s[m * 5 + 0]; s1 += v * s_W1s[m * 5 + 1]; s2 += v * s_W1s[m * 5 + 2];
        s3 += v * s_W1s[m * 5 + 3]; s4 += v * s_W1s[m * 5 + 4];
        r0 += v * s_W1r[m * 5 + 0]; r1 += v * s_W1r[m * 5 + 1]; r2 += v * s_W1r[m * 5 + 2];
        r3 += v * s_W1r[m * 5 + 3]; r4 += v * s_W1r[m * 5 + 4];
    }
    d_projs4[n] = make_float4(s0, s1, s2, s3);  d_projs1[n] = s4;
    d_projr4[n] = make_float4(r0, r1, r2, r3);  d_projr1[n] = r4;

    float4 z = make_float4(0.f, 0.f, 0.f, 0.f);
    d_accs4[n] = z;  d_accs1[n] = 0.f;
    d_accr4[n] = z;  d_accr1[n] = 0.f;
}

// ---------------------------------------------------------------------------
// Kernel 2: fused edge pass, 2 edges per thread.
// ---------------------------------------------------------------------------
__global__ void __launch_bounds__(THREADS)
edge_kernel(const float* __restrict__ ef,
            const int*   __restrict__ snd,
            const int*   __restrict__ rcv,
            const float* __restrict__ We2,
            const float* __restrict__ be2,
            int E)
{
    __shared__ float4 s_wt[40];     // [c][j]
    __shared__ float  s_w2[25];
    __shared__ float  s_b2[5];
    __shared__ float  s_hb[5];
    int t = threadIdx.x;
    if (t < 40) s_wt[t] = d_wcombT[t];
    if (t >= 64  && t < 89)  s_w2[t - 64]  = We2[t - 64];
    if (t >= 96  && t < 101) s_b2[t - 96]  = be2[t - 96];
    if (t >= 104 && t < 109) s_hb[t - 104] = d_hbase[t - 104];
    __syncthreads();

    int i0 = blockIdx.x * EPB + t;
    int i1 = i0 + THREADS;
    bool v0 = (i0 < E), v1 = (i1 < E);
    int iA = v0 ? i0 : (E - 1);
    int iB = v1 ? i1 : (E - 1);

    // indices (streamed, evict-first)
    int s0 = __ldcs(snd + iA), r0 = __ldcs(rcv + iA);
    int s1 = __ldcs(snd + iB), r1 = __ldcs(rcv + iB);

    // random gathers of precomputed projections (L2-resident hot arrays)
    float4 sp0 = __ldg(&d_projs4[s0]);  float sp0e = __ldg(&d_projs1[s0]);
    float4 rp0 = __ldg(&d_projr4[r0]);  float rp0e = __ldg(&d_projr1[r0]);
    float4 sp1 = __ldg(&d_projs4[s1]);  float sp1e = __ldg(&d_projs1[s1]);
    float4 rp1 = __ldg(&d_projr4[r1]);  float rp1e = __ldg(&d_projr1[r1]);

    const float4* xA = (const float4*)(ef + (size_t)iA * 32);
    const float4* xB = (const float4*)(ef + (size_t)iB * 32);

    float a0[5], a1[5];
    #pragma unroll
    for (int j = 0; j < 5; j++) { a0[j] = s_hb[j]; a1[j] = s_hb[j]; }

    // GEMM: both edges share the weight chunk loads
    #pragma unroll
    for (int c = 0; c < 8; c++) {
        float4 x0 = __ldcs(xA + c);    // streaming: don't pollute L2
        float4 x1 = __ldcs(xB + c);
        #pragma unroll
        for (int j = 0; j < 5; j++) {
            float4 w = s_wt[c * 5 + j];
            a0[j] += x0.x * w.x + x0.y * w.y + x0.z * w.z + x0.w * w.w;
            a1[j] += x1.x * w.x + x1.y * w.y + x1.z * w.z + x1.w * w.w;
        }
    }

    // edge 0: h -> e2 -> atomics
    {
        float h[5];
        h[0] = fmaxf(a0[0] + sp0.x + rp0.x, 0.f);
        h[1] = fmaxf(a0[1] + sp0.y + rp0.y, 0.f);
        h[2] = fmaxf(a0[2] + sp0.z + rp0.z, 0.f);
        h[3] = fmaxf(a0[3] + sp0.w + rp0.w, 0.f);
        h[4] = fmaxf(a0[4] + sp0e  + rp0e , 0.f);
        float o[5];
        #pragma unroll
        for (int j = 0; j < 5; j++) {
            float acc = s_b2[j];
            #pragma unroll
            for (int k = 0; k < 5; k++) acc += h[k] * s_w2[k * 5 + j];
            o[j] = fmaxf(acc, 0.f);
        }
        if (v0) {
            float4 ov = make_float4(o[0], o[1], o[2], o[3]);
            atomicAdd(&d_accs4[s0], ov);
            atomicAdd(&d_accs1[s0], o[4]);
            atomicAdd(&d_accr4[r0], ov);
            atomicAdd(&d_accr1[r0], o[4]);
        }
    }
    // edge 1
    {
        float h[5];
        h[0] = fmaxf(a1[0] + sp1.x + rp1.x, 0.f);
        h[1] = fmaxf(a1[1] + sp1.y + rp1.y, 0.f);
        h[2] = fmaxf(a1[2] + sp1.z + rp1.z, 0.f);
        h[3] = fmaxf(a1[3] + sp1.w + rp1.w, 0.f);
        h[4] = fmaxf(a1[4] + sp1e  + rp1e , 0.f);
        float o[5];
        #pragma unroll
        for (int j = 0; j < 5; j++) {
            float acc = s_b2[j];
            #pragma unroll
            for (int k = 0; k < 5; k++) acc += h[k] * s_w2[k * 5 + j];
            o[j] = fmaxf(acc, 0.f);
        }
        if (v1) {
            float4 ov = make_float4(o[0], o[1], o[2], o[3]);
            atomicAdd(&d_accs4[s1], ov);
            atomicAdd(&d_accs1[s1], o[4]);
            atomicAdd(&d_accr4[r1], ov);
            atomicAdd(&d_accr1[r1], o[4]);
        }
    }
}

// ---------------------------------------------------------------------------
// Kernel 3: node update epilogue.
// ---------------------------------------------------------------------------
__global__ void node_out_kernel(const float* __restrict__ Wn1,
                                const float* __restrict__ Wn2,
                                const float* __restrict__ bn2,
                                float* __restrict__ out,
                                int N)
{
    __shared__ float s_w1[75];
    __shared__ float s_w2[25];
    __shared__ float s_b2[5];
    __shared__ float s_gb[5];
    int t = threadIdx.x;
    if (t < 75) s_w1[t] = Wn1[t];
    if (t >= 96 && t < 121) s_w2[t - 96] = Wn2[t - 96];
    if (t >= 128 && t < 133) s_b2[t - 128] = bn2[t - 128];
    if (t >= 136 && t < 141) s_gb[t - 136] = d_gnbase[t - 136];
    __syncthreads();

    int n = blockIdx.x * THREADS + t;
    if (n >= N) return;

    float4 nv = d_nemb4[n];  float nv4 = d_nemb1[n];
    float4 sv = d_accs4[n];  float sv4 = d_accs1[n];
    float4 rv = d_accr4[n];  float rv4 = d_accr1[n];

    const float nn[5] = {nv.x, nv.y, nv.z, nv.w, nv4};
    const float ss[5] = {sv.x, sv.y, sv.z, sv.w, sv4};
    const float rr[5] = {rv.x, rv.y, rv.z, rv.w, rv4};

    float h[5];
    #pragma unroll
    for (int j = 0; j < 5; j++) {
        float acc = s_gb[j];
        #pragma unroll
        for (int m = 0; m < 5; m++) {
            acc += nn[m] * s_w1[m * 5 + j];
            acc += ss[m] * s_w1[(5 + m) * 5 + j];
            acc += rr[m] * s_w1[(10 + m) * 5 + j];
        }
        h[j] = fmaxf(acc, 0.f);
    }
    #pragma unroll
    for (int j = 0; j < 5; j++) {
        float acc = s_b2[j];
        #pragma unroll
        for (int k = 0; k < 5; k++) acc += h[k] * s_w2[k * 5 + j];
        out[(size_t)n * 5 + j] = fmaxf(acc, 0.f);
    }
}

// ---------------------------------------------------------------------------
extern "C" void kernel_launch(void* const* d_in, const int* in_sizes, int n_in,
                              void* d_out, int out_size)
{
    const float* node_feats  = (const float*)d_in[0];
    const float* edge_feats  = (const float*)d_in[1];
    const float* global_feat = (const float*)d_in[2];
    const int*   senders     = (const int*)  d_in[3];
    const int*   receivers   = (const int*)  d_in[4];
    const float* W_edge_emb  = (const float*)d_in[5];
    const float* b_edge_emb  = (const float*)d_in[6];
    const float* W_node_emb  = (const float*)d_in[7];
    const float* b_node_emb  = (const float*)d_in[8];
    const float* W_glob_emb  = (const float*)d_in[9];
    const float* b_glob_emb  = (const float*)d_in[10];
    const float* We1         = (const float*)d_in[11];
    const float* be1         = (const float*)d_in[12];
    const float* We2         = (const float*)d_in[13];
    const float* be2         = (const float*)d_in[14];
    const float* Wn1         = (const float*)d_in[15];
    const float* bn1         = (const float*)d_in[16];
    const float* Wn2         = (const float*)d_in[17];
    const float* bn2         = (const float*)d_in[18];
    float* out = (float*)d_out;

    int N = in_sizes[0] / 32;
    int E = in_sizes[1] / 32;

    prep_kernel<<<1, 256>>>(global_feat, W_glob_emb, b_glob_emb,
                            b_edge_emb, We1, be1, W_edge_emb, Wn1, bn1);

    node_pre_kernel<<<(N + THREADS - 1) / THREADS, THREADS>>>(
        node_feats, W_node_emb, b_node_emb, We1, N);

    edge_kernel<<<(E + EPB - 1) / EPB, THREADS>>>(
        edge_feats, senders, receivers, We2, be2, E);

    node_out_kernel<<<(N + THREADS - 1) / THREADS, THREADS>>>(
        Wn1, Wn2, bn2, out, N);
}